// round 13
// baseline (speedup 1.0000x reference)
#include <cuda_runtime.h>
#include <math.h>

#define TD    100
#define DLAT  64
#define DHID  128
#define NPG   64
#define KSZ   25
#define GQ    512
#define BT    256

typedef unsigned long long ull;
typedef unsigned int u32;

// Device scratch (zero-initialized at module load; no runtime allocations)
__device__ float g_Weff2[4 * 2048];   // [k][c 64][s 32], 4-float groups rotated by (c>>2)&7
__device__ float g_Wcat2[4 * 4096];   // [q][cc 32][j 128] plain transpose
__device__ float g_beff[DLAT];
__device__ u32   g_AdjB[GQ * NPG * NPG / 4]; // byte counts, 4/word; ALWAYS zero at entry
__device__ float g_Gsum[DHID];
__device__ float g_Gsq[DHID];
__device__ float g_S1[GQ * DHID];
__device__ float g_S2[GQ * DHID];
__device__ u32   g_done;              // last-CTA counter; ALWAYS zero at entry

__device__ __forceinline__ void fma2(ull& d, ull a, ull b) {
    asm("fma.rn.f32x2 %0, %1, %2, %0;" : "+l"(d) : "l"(a), "l"(b));
}
__device__ __forceinline__ ull dup2(float v) {
    ull r; asm("mov.b64 %0, {%1, %1};" : "=l"(r) : "f"(v)); return r;
}
__device__ __forceinline__ ull add2(ull a, ull b) {
    ull r; asm("add.rn.f32x2 %0, %1, %2;" : "=l"(r) : "l"(a), "l"(b)); return r;
}
__device__ __forceinline__ float lo32(ull v) { return __uint_as_float((unsigned)v); }
__device__ __forceinline__ float hi32(ull v) { return __uint_as_float((unsigned)(v >> 32)); }

// ---------------------------------------------------------------------------
// Kernel 0: setup — weight images + beff + Gsum/Gsq zero + byte-packed edge scatter
// ---------------------------------------------------------------------------
__global__ void setup_kernel(const float* __restrict__ conv_w, const float* __restrict__ conv_b,
                             const float* __restrict__ fc1_w, const float* __restrict__ fc1_b,
                             const float* __restrict__ rel_w, const float* __restrict__ root_w,
                             const int* __restrict__ ei, int Etot) {
    const int tid = blockIdx.x * blockDim.x + threadIdx.x;
    const int nth = gridDim.x * blockDim.x;

    if (blockIdx.x == 0) {
        int t = threadIdx.x;
        if (t < DHID) { g_Gsum[t] = 0.f; g_Gsq[t] = 0.f; }
        if (t < DLAT) {
            float sf = 0.f;
            for (int i = 0; i < TD; i++) sf += fc1_w[i];
            g_beff[t] = conv_b[t] * sf + fc1_b[0];
        }
    }
    for (int idx = tid; idx < DLAT * 128; idx += nth) {
        int c = idx >> 7, s = idx & 127;
        float w = 0.f;
        if (s < TD) {
            #pragma unroll
            for (int k = 0; k < KSZ; k++) {
                int tt = s + (KSZ / 2) - k;
                if (tt >= 0 && tt < TD) w += conv_w[c * KSZ + k] * fc1_w[tt];
            }
        }
        int kc = s >> 5, sl = s & 31;
        g_Weff2[kc * 2048 + c * 32 + (((sl & ~3) + 4 * ((c >> 2) & 7)) & 31) + (sl & 3)] = w;
    }
    for (int idx = tid; idx < DHID * DHID; idx += nth) {
        int j = idx >> 7, c = idx & 127;
        float w = (c < DLAT) ? rel_w[j * DLAT + c] : root_w[j * DLAT + (c - DLAT)];
        g_Wcat2[(c >> 5) * 4096 + (c & 31) * 128 + j] = w;
    }
    // Edge scatter: 8 edges/thread, byte-packed counts (max count per cell << 255)
    const int4* src4 = (const int4*)ei;
    const int4* dst4 = (const int4*)(ei + Etot);
    const int nv = Etot >> 3;
    for (int i = tid; i < nv; i += nth) {
        int4 sa = src4[2 * i], sb = src4[2 * i + 1];
        int4 da = dst4[2 * i], db = dst4[2 * i + 1];
        int e0 = 8 * i;
        int sv[8] = {sa.x, sa.y, sa.z, sa.w, sb.x, sb.y, sb.z, sb.w};
        int dv[8] = {da.x, da.y, da.z, da.w, db.x, db.y, db.z, db.w};
        #pragma unroll
        for (int k = 0; k < 8; k++) {
            int g = (e0 + k) & (GQ - 1);
            int cell = (g * NPG + (dv[k] & (NPG - 1))) * NPG + (sv[k] & (NPG - 1));
            atomicAdd(&g_AdjB[cell >> 2], 1u << ((cell & 3) * 8));
        }
    }
}

// ---------------------------------------------------------------------------
// Kernel 1: 2 graphs/CTA (256 CTAs) + fused final in last CTA. smem 96KB.
// ---------------------------------------------------------------------------
extern __shared__ float sm[];

#define P1_STEP(Xb, Wk, s4) {                                                  \
    ulonglong2 xu[8], wu[4];                                                   \
    _Pragma("unroll")                                                          \
    for (int ii = 0; ii < 8; ii++)                                             \
        xu[ii] = *(const ulonglong2*)&(Xb)[(8 * a + ii) * 32 + (s4)];          \
    _Pragma("unroll")                                                          \
    for (int jj = 0; jj < 4; jj++)                                             \
        wu[jj] = *(const ulonglong2*)&(Wk)[(4 * b + jj) * 32 + (((s4) + swb) & 31)]; \
    _Pragma("unroll")                                                          \
    for (int ii = 0; ii < 8; ii++)                                             \
        _Pragma("unroll")                                                      \
        for (int jj = 0; jj < 4; jj++) {                                       \
            fma2(acc1[ii][jj], xu[ii].x, wu[jj].x);                            \
            fma2(acc1[ii][jj], xu[ii].y, wu[jj].y);                            \
        }                                                                      \
}

__global__ void __launch_bounds__(BT, 2)
graph_kernel(const float* __restrict__ x, const float* __restrict__ rel_b,
             const float* __restrict__ bn_g, const float* __restrict__ bn_b,
             const float* __restrict__ fc2_w, const float* __restrict__ fc2_b,
             float* __restrict__ out, float invN) {
    const int bid = blockIdx.x;
    const int t = threadIdx.x;
    const int a = t >> 4, b = t & 15;
    const int swb = 4 * (b & 7);
    const int gg = a >> 3;

    float* WEF = sm;
    float* XB  = sm + 8192;
    float* H2N = sm + 16384;

    const float* xg = x + (size_t)bid * 128 * TD;

    #pragma unroll
    for (int q = 0; q < 8; q++)
        ((float4*)WEF)[t + BT * q] = ((const float4*)g_Weff2)[t + BT * q];
    #pragma unroll
    for (int q = 0; q < 4; q++) {
        int i4 = t + BT * q;
        int r = i4 >> 3, s0 = (i4 & 7) * 4;
        *(float4*)&XB[r * 32 + s0] = *(const float4*)&xg[r * TD + s0];
    }
    __syncthreads();

    // ---- Phase 1 ----
    ull acc1[8][4] = {};
    for (int k = 0; k < 3; k++) {
        const float* Xb = XB + (k & 1) * 4096;
        const float* Wk = WEF + k * 2048;
        float4 xn[4];
        #pragma unroll
        for (int q = 0; q < 4; q++) {
            int i4 = t + BT * q;
            int r = i4 >> 3, s0 = (k + 1) * 32 + (i4 & 7) * 4;
            xn[q] = (s0 < TD) ? *(const float4*)&xg[r * TD + s0]
                              : make_float4(0.f, 0.f, 0.f, 0.f);
        }
        #pragma unroll
        for (int si = 0; si < 8; si++) { P1_STEP(Xb, Wk, si * 4); }
        float* Xn = XB + ((k + 1) & 1) * 4096;
        #pragma unroll
        for (int q = 0; q < 4; q++) {
            int i4 = t + BT * q;
            int r = i4 >> 3, s0 = (i4 & 7) * 4;
            *(float4*)&Xn[r * 32 + s0] = xn[q];
        }
        __syncthreads();
    }
    // chunk 3 + adjacency byte prefetch / zero-after-read
    u32 aw[8];
    {
        u32* Aw = g_AdjB + bid * 2048;
        #pragma unroll
        for (int q = 0; q < 8; q++) aw[q] = Aw[t + BT * q];
        #pragma unroll
        for (int q = 0; q < 8; q++) Aw[t + BT * q] = 0u;
        P1_STEP(XB + 4096, WEF + 3 * 2048, 0);
    }
    {
        float4 bv = *(const float4*)&g_beff[4 * b];
        float br[4] = {bv.x, bv.y, bv.z, bv.w};
        #pragma unroll
        for (int ii = 0; ii < 8; ii++) {
            float4 o;
            o.x = lo32(acc1[ii][0]) + hi32(acc1[ii][0]) + br[0];
            o.y = lo32(acc1[ii][1]) + hi32(acc1[ii][1]) + br[1];
            o.z = lo32(acc1[ii][2]) + hi32(acc1[ii][2]) + br[2];
            o.w = lo32(acc1[ii][3]) + hi32(acc1[ii][3]) + br[3];
            *(float4*)&H2N[(8 * a + ii) * 64 + 4 * b] = o;
        }
    }
    __syncthreads();
    #pragma unroll
    for (int q = 0; q < 8; q++)      // expand bytes -> ADJ floats
        ((float4*)XB)[t + BT * q] = make_float4(
            (float)(aw[q] & 255u), (float)((aw[q] >> 8) & 255u),
            (float)((aw[q] >> 16) & 255u), (float)(aw[q] >> 24));
    __syncthreads();

    // ---- Phase 2 ----
    ull acc2[8][2] = {};
    float wc0[16];
    #pragma unroll
    for (int q = 0; q < 16; q++) wc0[q] = g_Wcat2[t + BT * q];
    {
        const float* ADJs = XB + gg * 4096;
        const float* H2g  = H2N + gg * 4096;
        #pragma unroll 4
        for (int si = 0; si < 16; si++) {
            int s4 = si * 4;
            float af[8][4];
            #pragma unroll
            for (int ii = 0; ii < 8; ii++) {
                float4 v = *(const float4*)&ADJs[(8 * (a & 7) + ii) * 64 + s4];
                af[ii][0] = v.x; af[ii][1] = v.y; af[ii][2] = v.z; af[ii][3] = v.w;
            }
            #pragma unroll
            for (int s2 = 0; s2 < 4; s2++) {
                ulonglong2 hv = *(const ulonglong2*)&H2g[(s4 + s2) * 64 + 4 * b];
                #pragma unroll
                for (int ii = 0; ii < 8; ii++) {
                    ull m2 = dup2(af[ii][s2]);
                    fma2(acc2[ii][0], m2, hv.x);
                    fma2(acc2[ii][1], m2, hv.y);
                }
            }
        }
    }
    __syncthreads();
    #pragma unroll
    for (int ii = 0; ii < 8; ii++)
        *(float4*)&XB[(8 * a + ii) * 64 + 4 * b] =
            make_float4(lo32(acc2[ii][0]), hi32(acc2[ii][0]),
                        lo32(acc2[ii][1]), hi32(acc2[ii][1]));
    #pragma unroll
    for (int q = 0; q < 16; q++) WEF[t + BT * q] = wc0[q];
    __syncthreads();

    // ---- Phase 3 ----
    ull acc3[8][4] = {};
    for (int q = 0; q < 4; q++) {
        const float* Wq = WEF + (q & 1) * 4096;
        float wn[16];
        if (q < 3) {
            #pragma unroll
            for (int r = 0; r < 16; r++) wn[r] = g_Wcat2[(q + 1) * 4096 + t + BT * r];
        }
        const float* M = (q < 2) ? XB : H2N;
        const int coff = (q & 1) * 32;
        #pragma unroll
        for (int ci = 0; ci < 8; ci++) {
            int c4 = ci * 4;
            float mf[8][4];
            #pragma unroll
            for (int ii = 0; ii < 8; ii++) {
                float4 v = *(const float4*)&M[(8 * a + ii) * 64 + coff + c4];
                mf[ii][0] = v.x; mf[ii][1] = v.y; mf[ii][2] = v.z; mf[ii][3] = v.w;
            }
            #pragma unroll
            for (int c2 = 0; c2 < 4; c2++) {
                ull wv[4];
                #pragma unroll
                for (int s = 0; s < 4; s++)
                    wv[s] = *(const ull*)&Wq[(c4 + c2) * 128 + 2 * b + 32 * s];
                #pragma unroll
                for (int ii = 0; ii < 8; ii++) {
                    ull m2 = dup2(mf[ii][c2]);
                    #pragma unroll
                    for (int s = 0; s < 4; s++) fma2(acc3[ii][s], m2, wv[s]);
                }
            }
        }
        if (q < 3) {
            float* Wn = WEF + ((q + 1) & 1) * 4096;
            #pragma unroll
            for (int r = 0; r < 16; r++) Wn[t + BT * r] = wn[r];
            __syncthreads();
        }
    }

    // ---- moments ----
    float* RED = WEF;
    #pragma unroll
    for (int s = 0; s < 4; s++) {
        ull rb = *(const ull*)&rel_b[2 * b + 32 * s];
        ull sum1 = 0ull, sum2 = 0ull;
        #pragma unroll
        for (int ii = 0; ii < 8; ii++) {
            ull v = add2(acc3[ii][s], rb);
            sum1 = add2(sum1, v);
            fma2(sum2, v, v);
        }
        int base = gg * 1024 + (a & 7) * 128 + 2 * b + 32 * s;
        *(ull*)&RED[base]        = sum1;
        *(ull*)&RED[2048 + base] = sum2;
    }
    __syncthreads();
    {
        int gg2 = t >> 7, j = t & 127;
        float S1 = 0.f, S2 = 0.f;
        #pragma unroll
        for (int ag = 0; ag < 8; ag++) {
            S1 += RED[gg2 * 1024 + ag * 128 + j];
            S2 += RED[2048 + gg2 * 1024 + ag * 128 + j];
        }
        int gl = bid * 2 + gg2;
        g_S1[gl * DHID + j] = S1;
        g_S2[gl * DHID + j] = S2;
        atomicAdd(&g_Gsum[j], S1);
        atomicAdd(&g_Gsq[j], S2);
    }

    // ---- fused final: last CTA computes BN -> pooled -> log -> fc2 -> sigmoid ----
    __threadfence();
    __syncthreads();
    __shared__ unsigned isLast;
    if (t == 0) isLast = (atomicAdd(&g_done, 1u) == (unsigned)(gridDim.x - 1)) ? 1u : 0u;
    __syncthreads();
    if (!isLast) return;
    if (t == 0) g_done = 0u;           // reset for next replay
    __threadfence();
    float* aas = sm;                   // [128]
    float* ccs = sm + 128;             // [128]
    float* f2s = sm + 256;             // [384]
    if (t < DHID) {
        float mu  = g_Gsum[t] * invN;
        float var = g_Gsq[t] * invN - mu * mu;
        float aa  = bn_g[t] * rsqrtf(var + 1e-5f);
        aas[t] = aa;
        ccs[t] = bn_b[t] - aa * mu;
        f2s[t]       = fc2_w[t];
        f2s[128 + t] = fc2_w[DHID + t];
        f2s[256 + t] = fc2_w[2 * DHID + t];
    }
    __syncthreads();
    const float b0 = fc2_b[0], b1 = fc2_b[1], b2 = fc2_b[2];
    for (int p = 0; p < 4; p++) {
        int g = p * 128 + (t >> 1);
        int jb = (t & 1) * 64;
        float p0 = 0.f, p1 = 0.f, p2 = 0.f;
        #pragma unroll 4
        for (int j0 = 0; j0 < 64; j0++) {
            int j = jb + j0;
            float aa = aas[j], cc = ccs[j];
            float s1 = g_S1[g * DHID + j], s2 = g_S2[g * DHID + j];
            float pooled = (aa * aa * s2 + 2.f * aa * cc * s1) * (1.f / 64.f) + cc * cc;
            float pl = logf(fmaxf(pooled, 1e-6f));
            p0 += pl * f2s[j]; p1 += pl * f2s[128 + j]; p2 += pl * f2s[256 + j];
        }
        p0 += __shfl_xor_sync(0xffffffffu, p0, 1);
        p1 += __shfl_xor_sync(0xffffffffu, p1, 1);
        p2 += __shfl_xor_sync(0xffffffffu, p2, 1);
        if ((t & 1) == 0) {
            out[g * 3 + 0] = 1.f / (1.f + expf(-(p0 + b0)));
            out[g * 3 + 1] = 1.f / (1.f + expf(-(p1 + b1)));
            out[g * 3 + 2] = 1.f / (1.f + expf(-(p2 + b2)));
        }
    }
}

// ---------------------------------------------------------------------------
extern "C" void kernel_launch(void* const* d_in, const int* in_sizes, int n_in,
                              void* d_out, int out_size) {
    const float* x      = (const float*)d_in[0];
    const int*   ei     = (const int*)d_in[1];     // int32 (JAX x64 disabled)
    const float* conv_w = (const float*)d_in[3];
    const float* conv_b = (const float*)d_in[4];
    const float* fc1_w  = (const float*)d_in[5];
    const float* fc1_b  = (const float*)d_in[6];
    const float* rel_w  = (const float*)d_in[7];
    const float* rel_b  = (const float*)d_in[8];
    const float* root_w = (const float*)d_in[9];
    const float* bn_g   = (const float*)d_in[10];
    const float* bn_b   = (const float*)d_in[11];
    const float* fc2_w  = (const float*)d_in[12];
    const float* fc2_b  = (const float*)d_in[13];
    float* out = (float*)d_out;

    const int Ntot = in_sizes[0] / TD;     // 32768
    const int G    = Ntot / NPG;           // 512
    const int Etot = in_sizes[1] / 2;      // 1048576

    const int smem_bytes = 24576 * 4;      // 96KB
    cudaFuncSetAttribute(graph_kernel, cudaFuncAttributeMaxDynamicSharedMemorySize, smem_bytes);

    setup_kernel<<<512, BT>>>(conv_w, conv_b, fc1_w, fc1_b, rel_w, root_w, ei, Etot);
    graph_kernel<<<G / 2, BT, smem_bytes>>>(x, rel_b, bn_g, bn_b, fc2_w, fc2_b,
                                            out, 1.0f / (float)Ntot);
}

// round 14
// speedup vs baseline: 2.2398x; 2.2398x over previous
#include <cuda_runtime.h>
#include <math.h>

#define TD    100
#define DLAT  64
#define DHID  128
#define NPG   64
#define KSZ   25
#define GQ    512
#define BT    256

typedef unsigned long long ull;
typedef unsigned int u32;

// Device scratch (zero-initialized at module load; no runtime allocations)
__device__ float g_Weff2[4 * 2048];   // [k][c 64][s 32], 4-float groups rotated by (c>>2)&7
__device__ float g_Wcat2[4 * 4096];   // [q][cc 32][j 128] plain transpose
__device__ float g_beff[DLAT];
__device__ u32   g_AdjB[GQ * NPG * NPG / 4]; // byte counts, 4/word; ALWAYS zero at entry
__device__ float g_Gsum[DHID];
__device__ float g_Gsq[DHID];
__device__ float g_S1[GQ * DHID];
__device__ float g_S2[GQ * DHID];

__device__ __forceinline__ void fma2(ull& d, ull a, ull b) {
    asm("fma.rn.f32x2 %0, %1, %2, %0;" : "+l"(d) : "l"(a), "l"(b));
}
__device__ __forceinline__ ull dup2(float v) {
    ull r; asm("mov.b64 %0, {%1, %1};" : "=l"(r) : "f"(v)); return r;
}
__device__ __forceinline__ ull add2(ull a, ull b) {
    ull r; asm("add.rn.f32x2 %0, %1, %2;" : "=l"(r) : "l"(a), "l"(b)); return r;
}
__device__ __forceinline__ float lo32(ull v) { return __uint_as_float((unsigned)v); }
__device__ __forceinline__ float hi32(ull v) { return __uint_as_float((unsigned)(v >> 32)); }

// ---------------------------------------------------------------------------
// Kernel 0: setup — weight images + beff + Gsum/Gsq zero + byte-packed edge scatter
// ---------------------------------------------------------------------------
__global__ void setup_kernel(const float* __restrict__ conv_w, const float* __restrict__ conv_b,
                             const float* __restrict__ fc1_w, const float* __restrict__ fc1_b,
                             const float* __restrict__ rel_w, const float* __restrict__ root_w,
                             const int* __restrict__ ei, int Etot) {
    const int tid = blockIdx.x * blockDim.x + threadIdx.x;
    const int nth = gridDim.x * blockDim.x;

    if (blockIdx.x == 0) {
        int t = threadIdx.x;
        if (t < DHID) { g_Gsum[t] = 0.f; g_Gsq[t] = 0.f; }
        if (t < DLAT) {
            float sf = 0.f;
            for (int i = 0; i < TD; i++) sf += fc1_w[i];
            g_beff[t] = conv_b[t] * sf + fc1_b[0];
        }
    }
    for (int idx = tid; idx < DLAT * 128; idx += nth) {
        int c = idx >> 7, s = idx & 127;
        float w = 0.f;
        if (s < TD) {
            #pragma unroll
            for (int k = 0; k < KSZ; k++) {
                int tt = s + (KSZ / 2) - k;
                if (tt >= 0 && tt < TD) w += conv_w[c * KSZ + k] * fc1_w[tt];
            }
        }
        int kc = s >> 5, sl = s & 31;
        g_Weff2[kc * 2048 + c * 32 + (((sl & ~3) + 4 * ((c >> 2) & 7)) & 31) + (sl & 3)] = w;
    }
    for (int idx = tid; idx < DHID * DHID; idx += nth) {
        int j = idx >> 7, c = idx & 127;
        float w = (c < DLAT) ? rel_w[j * DLAT + c] : root_w[j * DLAT + (c - DLAT)];
        g_Wcat2[(c >> 5) * 4096 + (c & 31) * 128 + j] = w;
    }
    // Edge scatter: 8 edges/thread, byte-packed counts (per-cell count << 255)
    const int4* src4 = (const int4*)ei;
    const int4* dst4 = (const int4*)(ei + Etot);
    const int nv = Etot >> 3;
    for (int i = tid; i < nv; i += nth) {
        int4 sa = src4[2 * i], sb = src4[2 * i + 1];
        int4 da = dst4[2 * i], db = dst4[2 * i + 1];
        int e0 = 8 * i;
        int sv[8] = {sa.x, sa.y, sa.z, sa.w, sb.x, sb.y, sb.z, sb.w};
        int dv[8] = {da.x, da.y, da.z, da.w, db.x, db.y, db.z, db.w};
        #pragma unroll
        for (int k = 0; k < 8; k++) {
            int g = (e0 + k) & (GQ - 1);
            int cell = (g * NPG + (dv[k] & (NPG - 1))) * NPG + (sv[k] & (NPG - 1));
            atomicAdd(&g_AdjB[cell >> 2], 1u << ((cell & 3) * 8));
        }
    }
}

// ---------------------------------------------------------------------------
// Kernel 1: 2 graphs/CTA (256 CTAs). smem 96KB. (No fused tail — it spills.)
// ---------------------------------------------------------------------------
extern __shared__ float sm[];

#define P1_STEP(Xb, Wk, s4) {                                                  \
    ulonglong2 xu[8], wu[4];                                                   \
    _Pragma("unroll")                                                          \
    for (int ii = 0; ii < 8; ii++)                                             \
        xu[ii] = *(const ulonglong2*)&(Xb)[(8 * a + ii) * 32 + (s4)];          \
    _Pragma("unroll")                                                          \
    for (int jj = 0; jj < 4; jj++)                                             \
        wu[jj] = *(const ulonglong2*)&(Wk)[(4 * b + jj) * 32 + (((s4) + swb) & 31)]; \
    _Pragma("unroll")                                                          \
    for (int ii = 0; ii < 8; ii++)                                             \
        _Pragma("unroll")                                                      \
        for (int jj = 0; jj < 4; jj++) {                                       \
            fma2(acc1[ii][jj], xu[ii].x, wu[jj].x);                            \
            fma2(acc1[ii][jj], xu[ii].y, wu[jj].y);                            \
        }                                                                      \
}

__global__ void __launch_bounds__(BT, 2)
graph_kernel(const float* __restrict__ x, const float* __restrict__ rel_b) {
    const int bid = blockIdx.x;
    const int t = threadIdx.x;
    const int a = t >> 4, b = t & 15;
    const int swb = 4 * (b & 7);
    const int gg = a >> 3;

    float* WEF = sm;
    float* XB  = sm + 8192;
    float* H2N = sm + 16384;

    const float* xg = x + (size_t)bid * 128 * TD;

    #pragma unroll
    for (int q = 0; q < 8; q++)
        ((float4*)WEF)[t + BT * q] = ((const float4*)g_Weff2)[t + BT * q];
    #pragma unroll
    for (int q = 0; q < 4; q++) {
        int i4 = t + BT * q;
        int r = i4 >> 3, s0 = (i4 & 7) * 4;
        *(float4*)&XB[r * 32 + s0] = *(const float4*)&xg[r * TD + s0];
    }
    __syncthreads();

    // ---- Phase 1 ----
    ull acc1[8][4] = {};
    for (int k = 0; k < 3; k++) {
        const float* Xb = XB + (k & 1) * 4096;
        const float* Wk = WEF + k * 2048;
        float4 xn[4];
        #pragma unroll
        for (int q = 0; q < 4; q++) {
            int i4 = t + BT * q;
            int r = i4 >> 3, s0 = (k + 1) * 32 + (i4 & 7) * 4;
            xn[q] = (s0 < TD) ? *(const float4*)&xg[r * TD + s0]
                              : make_float4(0.f, 0.f, 0.f, 0.f);
        }
        #pragma unroll
        for (int si = 0; si < 8; si++) { P1_STEP(Xb, Wk, si * 4); }
        float* Xn = XB + ((k + 1) & 1) * 4096;
        #pragma unroll
        for (int q = 0; q < 4; q++) {
            int i4 = t + BT * q;
            int r = i4 >> 3, s0 = (i4 & 7) * 4;
            *(float4*)&Xn[r * 32 + s0] = xn[q];
        }
        __syncthreads();
    }
    // chunk 3 + adjacency byte prefetch / zero-after-read
    u32 aw[8];
    {
        u32* Aw = g_AdjB + bid * 2048;
        #pragma unroll
        for (int q = 0; q < 8; q++) aw[q] = Aw[t + BT * q];
        #pragma unroll
        for (int q = 0; q < 8; q++) Aw[t + BT * q] = 0u;
        P1_STEP(XB + 4096, WEF + 3 * 2048, 0);
    }
    {
        float4 bv = *(const float4*)&g_beff[4 * b];
        float br[4] = {bv.x, bv.y, bv.z, bv.w};
        #pragma unroll
        for (int ii = 0; ii < 8; ii++) {
            float4 o;
            o.x = lo32(acc1[ii][0]) + hi32(acc1[ii][0]) + br[0];
            o.y = lo32(acc1[ii][1]) + hi32(acc1[ii][1]) + br[1];
            o.z = lo32(acc1[ii][2]) + hi32(acc1[ii][2]) + br[2];
            o.w = lo32(acc1[ii][3]) + hi32(acc1[ii][3]) + br[3];
            *(float4*)&H2N[(8 * a + ii) * 64 + 4 * b] = o;
        }
    }
    __syncthreads();
    #pragma unroll
    for (int q = 0; q < 8; q++)      // expand bytes -> ADJ floats
        ((float4*)XB)[t + BT * q] = make_float4(
            (float)(aw[q] & 255u), (float)((aw[q] >> 8) & 255u),
            (float)((aw[q] >> 16) & 255u), (float)(aw[q] >> 24));
    __syncthreads();

    // ---- Phase 2 ----
    ull acc2[8][2] = {};
    float wc0[16];
    #pragma unroll
    for (int q = 0; q < 16; q++) wc0[q] = g_Wcat2[t + BT * q];
    {
        const float* ADJs = XB + gg * 4096;
        const float* H2g  = H2N + gg * 4096;
        #pragma unroll 4
        for (int si = 0; si < 16; si++) {
            int s4 = si * 4;
            float af[8][4];
            #pragma unroll
            for (int ii = 0; ii < 8; ii++) {
                float4 v = *(const float4*)&ADJs[(8 * (a & 7) + ii) * 64 + s4];
                af[ii][0] = v.x; af[ii][1] = v.y; af[ii][2] = v.z; af[ii][3] = v.w;
            }
            #pragma unroll
            for (int s2 = 0; s2 < 4; s2++) {
                ulonglong2 hv = *(const ulonglong2*)&H2g[(s4 + s2) * 64 + 4 * b];
                #pragma unroll
                for (int ii = 0; ii < 8; ii++) {
                    ull m2 = dup2(af[ii][s2]);
                    fma2(acc2[ii][0], m2, hv.x);
                    fma2(acc2[ii][1], m2, hv.y);
                }
            }
        }
    }
    __syncthreads();
    #pragma unroll
    for (int ii = 0; ii < 8; ii++)
        *(float4*)&XB[(8 * a + ii) * 64 + 4 * b] =
            make_float4(lo32(acc2[ii][0]), hi32(acc2[ii][0]),
                        lo32(acc2[ii][1]), hi32(acc2[ii][1]));
    #pragma unroll
    for (int q = 0; q < 16; q++) WEF[t + BT * q] = wc0[q];
    __syncthreads();

    // ---- Phase 3 ----
    ull acc3[8][4] = {};
    for (int q = 0; q < 4; q++) {
        const float* Wq = WEF + (q & 1) * 4096;
        float wn[16];
        if (q < 3) {
            #pragma unroll
            for (int r = 0; r < 16; r++) wn[r] = g_Wcat2[(q + 1) * 4096 + t + BT * r];
        }
        const float* M = (q < 2) ? XB : H2N;
        const int coff = (q & 1) * 32;
        #pragma unroll
        for (int ci = 0; ci < 8; ci++) {
            int c4 = ci * 4;
            float mf[8][4];
            #pragma unroll
            for (int ii = 0; ii < 8; ii++) {
                float4 v = *(const float4*)&M[(8 * a + ii) * 64 + coff + c4];
                mf[ii][0] = v.x; mf[ii][1] = v.y; mf[ii][2] = v.z; mf[ii][3] = v.w;
            }
            #pragma unroll
            for (int c2 = 0; c2 < 4; c2++) {
                ull wv[4];
                #pragma unroll
                for (int s = 0; s < 4; s++)
                    wv[s] = *(const ull*)&Wq[(c4 + c2) * 128 + 2 * b + 32 * s];
                #pragma unroll
                for (int ii = 0; ii < 8; ii++) {
                    ull m2 = dup2(mf[ii][c2]);
                    #pragma unroll
                    for (int s = 0; s < 4; s++) fma2(acc3[ii][s], m2, wv[s]);
                }
            }
        }
        if (q < 3) {
            float* Wn = WEF + ((q + 1) & 1) * 4096;
            #pragma unroll
            for (int r = 0; r < 16; r++) Wn[t + BT * r] = wn[r];
            __syncthreads();
        }
    }

    // ---- moments ----
    float* RED = WEF;
    #pragma unroll
    for (int s = 0; s < 4; s++) {
        ull rb = *(const ull*)&rel_b[2 * b + 32 * s];
        ull sum1 = 0ull, sum2 = 0ull;
        #pragma unroll
        for (int ii = 0; ii < 8; ii++) {
            ull v = add2(acc3[ii][s], rb);
            sum1 = add2(sum1, v);
            fma2(sum2, v, v);
        }
        int base = gg * 1024 + (a & 7) * 128 + 2 * b + 32 * s;
        *(ull*)&RED[base]        = sum1;
        *(ull*)&RED[2048 + base] = sum2;
    }
    __syncthreads();
    {
        int gg2 = t >> 7, j = t & 127;
        float S1 = 0.f, S2 = 0.f;
        #pragma unroll
        for (int ag = 0; ag < 8; ag++) {
            S1 += RED[gg2 * 1024 + ag * 128 + j];
            S2 += RED[2048 + gg2 * 1024 + ag * 128 + j];
        }
        int gl = bid * 2 + gg2;
        g_S1[gl * DHID + j] = S1;
        g_S2[gl * DHID + j] = S2;
        atomicAdd(&g_Gsum[j], S1);
        atomicAdd(&g_Gsq[j], S2);
    }
}

// ---------------------------------------------------------------------------
// Kernel 2: BN stats -> pooled moments -> log -> fc2 -> sigmoid (2 graphs/CTA)
// ---------------------------------------------------------------------------
__global__ void final_kernel(const float* __restrict__ bn_g, const float* __restrict__ bn_b,
                             const float* __restrict__ fc2_w, const float* __restrict__ fc2_b,
                             float* __restrict__ out, float invN) {
    int t = threadIdx.x;
    int h = t >> 7;
    int g = blockIdx.x * 2 + h;
    int j = t & 127;
    float mu  = g_Gsum[j] * invN;
    float var = g_Gsq[j] * invN - mu * mu;
    float aa  = bn_g[j] * rsqrtf(var + 1e-5f);
    float cc  = bn_b[j] - aa * mu;
    float s1  = g_S1[g * DHID + j];
    float s2  = g_S2[g * DHID + j];
    float pooled = (aa * aa * s2 + 2.f * aa * cc * s1) * (1.f / 64.f) + cc * cc;
    float pl = logf(fmaxf(pooled, 1e-6f));
    float p0 = pl * fc2_w[j];
    float p1 = pl * fc2_w[DHID + j];
    float p2 = pl * fc2_w[2 * DHID + j];
    #pragma unroll
    for (int off = 16; off > 0; off >>= 1) {
        p0 += __shfl_down_sync(0xffffffffu, p0, off);
        p1 += __shfl_down_sync(0xffffffffu, p1, off);
        p2 += __shfl_down_sync(0xffffffffu, p2, off);
    }
    __shared__ float r[24];
    if ((t & 31) == 0) {
        int w = t >> 5;
        r[w * 3 + 0] = p0; r[w * 3 + 1] = p1; r[w * 3 + 2] = p2;
    }
    __syncthreads();
    if (j < 3) {
        int base = h * 12;
        float v = r[base + j] + r[base + 3 + j] + r[base + 6 + j] + r[base + 9 + j] + fc2_b[j];
        out[g * 3 + j] = 1.f / (1.f + expf(-v));
    }
}

// ---------------------------------------------------------------------------
extern "C" void kernel_launch(void* const* d_in, const int* in_sizes, int n_in,
                              void* d_out, int out_size) {
    const float* x      = (const float*)d_in[0];
    const int*   ei     = (const int*)d_in[1];     // int32 (JAX x64 disabled)
    const float* conv_w = (const float*)d_in[3];
    const float* conv_b = (const float*)d_in[4];
    const float* fc1_w  = (const float*)d_in[5];
    const float* fc1_b  = (const float*)d_in[6];
    const float* rel_w  = (const float*)d_in[7];
    const float* rel_b  = (const float*)d_in[8];
    const float* root_w = (const float*)d_in[9];
    const float* bn_g   = (const float*)d_in[10];
    const float* bn_b   = (const float*)d_in[11];
    const float* fc2_w  = (const float*)d_in[12];
    const float* fc2_b  = (const float*)d_in[13];
    float* out = (float*)d_out;

    const int Ntot = in_sizes[0] / TD;     // 32768
    const int G    = Ntot / NPG;           // 512
    const int Etot = in_sizes[1] / 2;      // 1048576

    const int smem_bytes = 24576 * 4;      // 96KB
    cudaFuncSetAttribute(graph_kernel, cudaFuncAttributeMaxDynamicSharedMemorySize, smem_bytes);

    setup_kernel<<<512, BT>>>(conv_w, conv_b, fc1_w, fc1_b, rel_w, root_w, ei, Etot);
    graph_kernel<<<G / 2, BT, smem_bytes>>>(x, rel_b);
    final_kernel<<<G / 2, BT>>>(bn_g, bn_b, fc2_w, fc2_b, out, 1.0f / (float)Ntot);
}